// round 6
// baseline (speedup 1.0000x reference)
#include <cuda_runtime.h>
#include <math.h>

#define H 4096
#define EPS 1e-5f
#define ROWS_PER_BLOCK 8
#define NBLOCKS (5 * H / ROWS_PER_BLOCK)   // 2560, 512 blocks per z-part
#define EBLOCKS 16
#define ETHR 64                             // 16*64 = 1024 float4 = H/4

// Scratch + accumulators (no device allocation allowed).
__device__ float g_z[5 * H];
__device__ float g_sum[5]   = {0.f, 0.f, 0.f, 0.f, 0.f};
__device__ float g_sumsq[5] = {0.f, 0.f, 0.f, 0.f, 0.f};
__device__ float g_csum   = 0.f;
__device__ float g_csumsq = 0.f;
__device__ unsigned int g_cnt  = 0;
__device__ unsigned int g_done = 0;

__device__ __forceinline__ float sigmoidf_(float x) {
    return 1.0f / (1.0f + __expf(-x));
}
// tanh(x) = 1 - 2/(exp(2x)+1); saturates correctly at +/-inf.
__device__ __forceinline__ float tanhf_(float x) {
    return 1.0f - 2.0f / (__expf(2.0f * x) + 1.0f);
}

// ---------------------------------------------------------------------------
// Kernel 1: GEMV  z[r] = dot(W[r, 0:2H], [h0;h1]) ; one warp per row.
// W streamed via __ldcs; dot product uses packed fma.rn.f32x2 (FFMA2) to
// halve FMA instruction count. Early PDL trigger lets the epilogue's
// prologue overlap the GEMV stream.
// ---------------------------------------------------------------------------
__global__ __launch_bounds__(256, 4)
void gemv_kernel(const float* __restrict__ h0,
                 const float* __restrict__ h1,
                 const float* __restrict__ W)
{
    __shared__ float xs[2 * H];
    __shared__ float rs[8], rq[8];

    cudaTriggerProgrammaticLaunchCompletion();

    const int tid = threadIdx.x;

    const float4* h0v = reinterpret_cast<const float4*>(h0);
    const float4* h1v = reinterpret_cast<const float4*>(h1);
    float4* xsv = reinterpret_cast<float4*>(xs);
    #pragma unroll
    for (int i = tid; i < H / 4; i += 256) {
        xsv[i]         = h0v[i];
        xsv[i + H / 4] = h1v[i];
    }
    __syncthreads();

    const int warp = tid >> 5;
    const int lane = tid & 31;
    const int row  = blockIdx.x * ROWS_PER_BLOCK + warp;

    const ulonglong2* wrow =
        reinterpret_cast<const ulonglong2*>(W + (size_t)row * (2 * H));
    const ulonglong2* xs2 = reinterpret_cast<const ulonglong2*>(xs);

    // Two packed f32x2 accumulators (= 4 fp32 lanes, same grouping as before).
    unsigned long long acc0 = 0ull, acc1 = 0ull;   // {0.0f, 0.0f}
    #pragma unroll 8
    for (int i = lane; i < (2 * H) / 4; i += 32) {
        ulonglong2 w = __ldcs(&wrow[i]);
        ulonglong2 x = xs2[i];
        asm("fma.rn.f32x2 %0, %1, %2, %0;" : "+l"(acc0) : "l"(w.x), "l"(x.x));
        asm("fma.rn.f32x2 %0, %1, %2, %0;" : "+l"(acc1) : "l"(w.y), "l"(x.y));
    }
    float a0, a1, a2, a3;
    asm("mov.b64 {%0, %1}, %2;" : "=f"(a0), "=f"(a1) : "l"(acc0));
    asm("mov.b64 {%0, %1}, %2;" : "=f"(a2), "=f"(a3) : "l"(acc1));

    float s = (a0 + a1) + (a2 + a3);
    #pragma unroll
    for (int off = 16; off > 0; off >>= 1)
        s += __shfl_down_sync(0xffffffffu, s, off);

    if (lane == 0) {
        g_z[row] = s;
        rs[warp] = s;
        rq[warp] = s * s;
    }
    __syncthreads();

    if (tid == 0) {
        float bs = 0.f, bq = 0.f;
        #pragma unroll
        for (int w = 0; w < 8; w++) { bs += rs[w]; bq += rq[w]; }
        const int part = blockIdx.x >> 9;     // 512 blocks per part
        atomicAdd(&g_sum[part],   bs);
        atomicAdd(&g_sumsq[part], bq);
    }
}

// ---------------------------------------------------------------------------
// Kernel 2: epilogue, 16 CTAs x 64 threads, launched with PDL. Prefetches all
// GEMV-independent inputs into registers BEFORE cudaGridDependencySynchronize,
// so only the z-dependent tail is exposed after the GEMV drains.
// ---------------------------------------------------------------------------
__global__ __launch_bounds__(ETHR, 1)
void epilogue_kernel(const float* __restrict__ c0,
                     const float* __restrict__ c1,
                     const float* __restrict__ ffio_g,
                     const float* __restrict__ ffio_b,
                     const float* __restrict__ u_g,
                     const float* __restrict__ u_b,
                     const float* __restrict__ c_g,
                     const float* __restrict__ c_b,
                     float* __restrict__ out)
{
    const int t    = threadIdx.x;   // 0..63
    const int warp = t >> 5;
    const int lane = t & 31;
    const int g    = blockIdx.x * ETHR + t;   // float4 index 0..1023

    __shared__ float red_s[2], red_q[2];
    __shared__ float s_mc, s_rc;

    // ---- Prefetch GEMV-independent inputs (overlaps the GEMV stream) -------
    float4 fg[4], fb[4];
    #pragma unroll
    for (int p = 0; p < 4; p++) {
        fg[p] = reinterpret_cast<const float4*>(ffio_g + p * H)[g];
        fb[p] = reinterpret_cast<const float4*>(ffio_b + p * H)[g];
    }
    float4 ugv = reinterpret_cast<const float4*>(u_g)[g];
    float4 ubv = reinterpret_cast<const float4*>(u_b)[g];
    float4 c0v = reinterpret_cast<const float4*>(c0)[g];
    float4 c1v = reinterpret_cast<const float4*>(c1)[g];
    float4 cgv = reinterpret_cast<const float4*>(c_g)[g];
    float4 cbv = reinterpret_cast<const float4*>(c_b)[g];

    // ---- Wait for GEMV completion (memory visible afterwards) --------------
    cudaGridDependencySynchronize();

    // Part statistics (accumulated by kernel 1).
    float m5[5], r5[5];
    #pragma unroll
    for (int p = 0; p < 5; p++) {
        float mean = g_sum[p] * (1.0f / H);
        float var  = g_sumsq[p] * (1.0f / H) - mean * mean;
        m5[p] = mean;
        r5[p] = rsqrtf(var + EPS);
    }

    const float4* gz4 = reinterpret_cast<const float4*>(g_z);

    float v[5][4];
    #pragma unroll
    for (int p = 0; p < 5; p++) {
        float4 vv = gz4[p * (H / 4) + g];
        v[p][0] = vv.x; v[p][1] = vv.y; v[p][2] = vv.z; v[p][3] = vv.w;
    }

    float gate[4][4];
    #pragma unroll
    for (int p = 0; p < 4; p++) {
        float ga[4] = {fg[p].x, fg[p].y, fg[p].z, fg[p].w};
        float ba[4] = {fb[p].x, fb[p].y, fb[p].z, fb[p].w};
        float m = m5[p], r = r5[p];
        #pragma unroll
        for (int k = 0; k < 4; k++)
            gate[p][k] = sigmoidf_(fmaf((v[p][k] - m) * r, ga[k], ba[k]));
    }

    float uval[4];
    {
        float m = m5[4], r = r5[4];
        uval[0] = tanhf_(fmaf((v[4][0] - m) * r, ugv.x, ubv.x));
        uval[1] = tanhf_(fmaf((v[4][1] - m) * r, ugv.y, ubv.y));
        uval[2] = tanhf_(fmaf((v[4][2] - m) * r, ugv.z, ubv.z));
        uval[3] = tanhf_(fmaf((v[4][3] - m) * r, ugv.w, ubv.w));
    }

    float c0a[4] = {c0v.x, c0v.y, c0v.z, c0v.w};
    float c1a[4] = {c1v.x, c1v.y, c1v.z, c1v.w};

    float cell[4];
    #pragma unroll
    for (int k = 0; k < 4; k++)
        cell[k] = fmaf(gate[2][k], uval[k],
                  fmaf(gate[0][k], c0a[k], gate[1][k] * c1a[k]));

    // Block partial (sum, sumsq) of cell
    {
        float s = (cell[0] + cell[1]) + (cell[2] + cell[3]);
        float q = fmaf(cell[0], cell[0], fmaf(cell[1], cell[1],
                  fmaf(cell[2], cell[2], cell[3] * cell[3])));
        #pragma unroll
        for (int off = 16; off > 0; off >>= 1) {
            s += __shfl_down_sync(0xffffffffu, s, off);
            q += __shfl_down_sync(0xffffffffu, q, off);
        }
        if (lane == 0) { red_s[warp] = s; red_q[warp] = q; }
    }
    __syncthreads();

    // Thread 0: publish partials, arrive, spin until all 16 blocks arrived.
    if (t == 0) {
        atomicAdd(&g_csum,   red_s[0] + red_s[1]);
        atomicAdd(&g_csumsq, red_q[0] + red_q[1]);
        __threadfence();
        atomicAdd(&g_cnt, 1u);
        while (*((volatile unsigned int*)&g_cnt) < EBLOCKS)
            __nanosleep(32);
        __threadfence();
        float cs = atomicAdd(&g_csum,   0.0f);
        float cq = atomicAdd(&g_csumsq, 0.0f);
        float mean = cs * (1.0f / H);
        float var  = cq * (1.0f / H) - mean * mean;
        s_mc = mean;
        s_rc = rsqrtf(var + EPS);
    }
    __syncthreads();

    // Final LN on cell + outputs
    const float m = s_mc, r = s_rc;
    float cga[4] = {cgv.x, cgv.y, cgv.z, cgv.w};
    float cba[4] = {cbv.x, cbv.y, cbv.z, cbv.w};

    float4 hid, ncl;
    float nc[4], hd[4];
    #pragma unroll
    for (int k = 0; k < 4; k++) {
        nc[k] = fmaf((cell[k] - m) * r, cga[k], cba[k]);
        hd[k] = gate[3][k] * tanhf_(nc[k]);
    }
    hid.x = hd[0]; hid.y = hd[1]; hid.z = hd[2]; hid.w = hd[3];
    ncl.x = nc[0]; ncl.y = nc[1]; ncl.z = nc[2]; ncl.w = nc[3];

    reinterpret_cast<float4*>(out)[g]     = hid;   // new_hidden
    reinterpret_cast<float4*>(out + H)[g] = ncl;   // new_cell

    // Last block to finish resets all cross-launch state for graph replay.
    __syncthreads();
    if (t == 0) {
        unsigned int prev = atomicAdd(&g_done, 1u);
        if (prev == EBLOCKS - 1) {
            g_cnt = 0; g_done = 0;
            g_csum = 0.f; g_csumsq = 0.f;
            #pragma unroll
            for (int p = 0; p < 5; p++) { g_sum[p] = 0.f; g_sumsq[p] = 0.f; }
        }
    }
}

// ---------------------------------------------------------------------------
// Inputs (metadata order): 0=h0, 1=c0, 2=h1, 3=c1, 4=W,
//   5=ffio_g(4H), 6=ffio_b(4H), 7=u_g, 8=u_b, 9=c_g, 10=c_b
// Output: [new_hidden(4096); new_cell(4096)] fp32
// ---------------------------------------------------------------------------
extern "C" void kernel_launch(void* const* d_in, const int* in_sizes, int n_in,
                              void* d_out, int out_size)
{
    const float* h0     = (const float*)d_in[0];
    const float* c0     = (const float*)d_in[1];
    const float* h1     = (const float*)d_in[2];
    const float* c1     = (const float*)d_in[3];
    const float* W      = (const float*)d_in[4];
    const float* ffio_g = (const float*)d_in[5];
    const float* ffio_b = (const float*)d_in[6];
    const float* u_g    = (const float*)d_in[7];
    const float* u_b    = (const float*)d_in[8];
    const float* c_g    = (const float*)d_in[9];
    const float* c_b    = (const float*)d_in[10];
    float* out = (float*)d_out;

    gemv_kernel<<<NBLOCKS, 256>>>(h0, h1, W);

    // Epilogue launched with programmatic dependent launch: its prologue
    // (parameter prefetch) overlaps the GEMV; cudaGridDependencySynchronize
    // inside the kernel enforces the data dependency on g_z / g_sum.
    cudaLaunchConfig_t cfg = {};
    cfg.gridDim  = dim3(EBLOCKS, 1, 1);
    cfg.blockDim = dim3(ETHR, 1, 1);
    cfg.dynamicSmemBytes = 0;
    cfg.stream = 0;
    cudaLaunchAttribute attr[1];
    attr[0].id = cudaLaunchAttributeProgrammaticStreamSerialization;
    attr[0].val.programmaticStreamSerializationAllowed = 1;
    cfg.attrs = attr;
    cfg.numAttrs = 1;
    cudaLaunchKernelEx(&cfg, epilogue_kernel,
                       c0, c1, ffio_g, ffio_b, u_g, u_b, c_g, c_b, out);
}